// round 12
// baseline (speedup 1.0000x reference)
#include <cuda_runtime.h>

// Problem constants
#define B_ 8
#define C_ 256
#define N_ 16384
#define K_ 128

// Decomposition: CTA = (batch, 64-channel slice, 1-of-9 N interleave)
#define SLICE_C 64
#define NSLICE 4                // C_/SLICE_C
#define NS 9                    // N interleave -> 8*4*9 = 288 CTAs, 2/SM
#define TN 64                   // points per chunk
#define TPB 512
#define NCHUNKS (N_ / TN)       // 256 chunks, round-robin over NS
#define TROW 68                 // padded row stride (floats/uints)
#define TAB_U (K_ * TROW)       // 8704 uints per-CTA table

// Per-CTA partial tables: 288 x 34.8KB ~= 10 MB.
__device__ unsigned int g_scratch[B_ * NSLICE * NS * TAB_U];

// Monotone float -> uint key: unsigned order == float order.
__device__ __forceinline__ unsigned int fkey(float f) {
    int i = __float_as_int(f);
    return (i >= 0) ? ((unsigned int)i | 0x80000000u) : ~(unsigned int)i;
}
__device__ __forceinline__ float funkey(unsigned int k) {
    unsigned int i = (k & 0x80000000u) ? (k & 0x7FFFFFFFu) : ~k;
    return __int_as_float((int)i);
}

// Branch-free conditional shared max: SETP + @p RED.SHARED.
__device__ __forceinline__ void smax_if(unsigned int* cell, unsigned int cur,
                                        unsigned int key) {
    unsigned int addr = (unsigned int)__cvta_generic_to_shared(cell);
    asm volatile(
        "{\n\t.reg .pred p;\n\t"
        "setp.lt.u32 p, %1, %2;\n\t"
        "@p red.shared.max.u32 [%0], %2;\n\t}"
        :: "r"(addr), "r"(cur), "r"(key) : "memory");
}

// Phase 1: fused transpose + per-CTA segment-max, 2-deep reg pipeline, 2 CTAs/SM.
__global__ __launch_bounds__(TPB, 2)
void seg_phase1(const float* __restrict__ pf, const int* __restrict__ cids,
                float* __restrict__ out_pf) {
    extern __shared__ unsigned int smem[];
    unsigned int* tab = smem;                          // [K][TROW], 34.8 KB
    float* tile = (float*)(smem + TAB_U);              // [TN][TROW] point-major
    int* scid = (int*)(tile + TN * TROW);              // TN ids

    const int tid = threadIdx.x;
    const int b = blockIdx.y;
    const int cslice = blockIdx.x / NS;                // 0..3
    const int ns = blockIdx.x - cslice * NS;           // 0..8

    {   // init table
        uint4 z = make_uint4(0u, 0u, 0u, 0u);
        uint4* t4 = (uint4*)tab;
        #pragma unroll
        for (int i = tid; i < TAB_U / 4; i += TPB) t4[i] = z;
    }

    const float* src = pf + (size_t)b * C_ * N_ + (size_t)cslice * SLICE_C * N_;
    const int* cidp = cids + b * N_;

    // chunk count for this ns: 256 = 9*28 + 4 -> ns<4 get 29, else 28
    const int cnt = (NCHUNKS / NS) + (ns < (NCHUNKS % NS) ? 1 : 0);

    // Loader: thread owns point ln, channel quads cg4 and cg4+32 (in-slice)
    const int ln = tid & 63;
    const int cg4 = (tid >> 6) * 4;     // 0,4,...,28
    // Consumer: 4 consecutive channels per thread; warp = 2 points
    const int c4 = (tid & 15) * 4;      // 0..60
    const int pb = tid >> 4;            // 0..31

    auto prefetch = [&](int i, float* rr, int& cidr) {
        const int m = ns + NS * i;
        const float* p0 = src + (size_t)cg4 * N_ + m * TN + ln;
        #pragma unroll
        for (int j = 0; j < 4; j++) {
            rr[j]     = __ldcs(p0 + (size_t)j * N_);
            rr[4 + j] = __ldcs(p0 + (size_t)(32 + j) * N_);
        }
        if (tid < TN) cidr = cidp[m * TN + tid];
    };

    float rA[8], rB[8];
    int cidA = 0, cidB = 0;
    prefetch(0, rA, cidA);
    if (cnt > 1) prefetch(1, rB, cidB);

    auto body = [&](int i, float* rr, int& cidr) {
        __syncthreads();                               // prev tile fully consumed
        *(float4*)(tile + ln * TROW + cg4)      = make_float4(rr[0], rr[1], rr[2], rr[3]);
        *(float4*)(tile + ln * TROW + cg4 + 32) = make_float4(rr[4], rr[5], rr[6], rr[7]);
        if (tid < TN) scid[tid] = cidr;
        __syncthreads();                               // tile + scid ready

        if (i + 2 < cnt) prefetch(i + 2, rr, cidr);    // refill freed buffer

        const int n0 = (ns + NS * i) * TN;
        #pragma unroll
        for (int q = 0; q < 2; q++) {
            const int p = pb + q * 32;
            float4 vv = *(const float4*)(tile + p * TROW + c4);
            __stcs((float4*)(out_pf + ((size_t)b * N_ + n0 + p) * C_
                             + cslice * SLICE_C + c4), vv);
            const int cid = scid[p];
            const int en = (cid >= 0);
            unsigned int* cell = &tab[(en ? cid : 0) * TROW + c4];
            uint4 cur = *(const uint4*)cell;           // LDS.128 filter read
            unsigned int k0 = en ? fkey(vv.x) : 0u;
            unsigned int k1 = en ? fkey(vv.y) : 0u;
            unsigned int k2 = en ? fkey(vv.z) : 0u;
            unsigned int k3 = en ? fkey(vv.w) : 0u;
            smax_if(cell + 0, cur.x, k0);
            smax_if(cell + 1, cur.y, k1);
            smax_if(cell + 2, cur.z, k2);
            smax_if(cell + 3, cur.w, k3);
        }
    };

    int i = 0;
    #pragma unroll 1
    for (; i + 1 < cnt; i += 2) {
        body(i,     rA, cidA);
        body(i + 1, rB, cidB);
    }
    if (i < cnt) body(i, rA, cidA);                    // odd tail
    __syncthreads();

    // dump table (plain stores)
    uint4* dst = (uint4*)(g_scratch
                 + (size_t)((b * NSLICE + cslice) * NS + ns) * TAB_U);
    const uint4* t4 = (const uint4*)tab;
    #pragma unroll
    for (int i2 = tid; i2 < TAB_U / 4; i2 += TPB) dst[i2] = t4[i2];
}

// Phase 2: one thread per output scalar — 262144 threads, 9 independent 4B
// loads each (MLP=9), no shuffles. out index == global thread id.
__global__ __launch_bounds__(256)
void seg_phase2(float* __restrict__ out_seg) {
    int g = blockIdx.x * blockDim.x + threadIdx.x;     // 0 .. B*K*C-1
    int c = g & (C_ - 1);                              // channel 0..255
    int k = (g >> 8) & (K_ - 1);                       // cluster 0..127
    int b = g >> 15;                                   // batch 0..7
    int slice = c >> 6;
    int cc = c & (SLICE_C - 1);
    const unsigned int* base = g_scratch
        + (size_t)((b * NSLICE + slice) * NS) * TAB_U + k * TROW + cc;
    unsigned int mx = 0u;
    #pragma unroll
    for (int s = 0; s < NS; s++)
        mx = max(mx, base[(size_t)s * TAB_U]);
    out_seg[g] = mx ? funkey(mx) : 0.0f;
}

extern "C" void kernel_launch(void* const* d_in, const int* in_sizes, int n_in,
                              void* d_out, int out_size) {
    const float* pf = (const float*)d_in[0];      // (B,C,N) f32
    const int* cid  = (const int*)d_in[1];        // (B,N) i32
    float* out      = (float*)d_out;
    float* out_seg  = out;                        // (B*K, C)
    float* out_pf   = out + (size_t)B_ * K_ * C_; // (B*N, C)

    const size_t smem_bytes = (size_t)TAB_U * 4 + (size_t)TN * TROW * 4 + (size_t)TN * 4;
    cudaFuncSetAttribute(seg_phase1, cudaFuncAttributeMaxDynamicSharedMemorySize,
                         (int)smem_bytes);

    dim3 grid(NSLICE * NS, B_);                   // 36 x 8 = 288 CTAs, 2/SM
    seg_phase1<<<grid, TPB, smem_bytes>>>(pf, cid, out_pf);

    seg_phase2<<<(B_ * K_ * C_) / 256, 256>>>(out_seg);
}